// round 16
// baseline (speedup 1.0000x reference)
#include <cuda_runtime.h>
#include <cuda_bf16.h>

// Problem constants
#define C_IN  64
#define C_OUT 64
#define XD 32
#define XH 64
#define XW 64
#define OD 64
#define OH 128
#define OW 128
#define ZD 68
#define ZH 132
#define ZW 132

#define X_CH_STRIDE (XD*XH*XW)      // 131072 floats
#define O_CH_STRIDE (OD*OH*OW)      // 1048576 floats

#define NUM_CONV_BLOCKS 1024        // 32 dp * 32 hq (2 h' rows each, full w)
#define NUM_COPY_BLOCKS 4096
#define NUM_BLOCKS (NUM_CONV_BLOCKS + NUM_COPY_BLOCKS)   // 5120, 1-in-5 conv

#define WT_PITCH 68                 // >=64 (R12 lesson); 17 float4 per c-row
#define YS_FLOATS (64 * 128)        // ys[o][hp][w'] = 64 x 2 x 64
#define SMEM_BYTES ((64 * WT_PITCH + YS_FLOATS) * 4)   // 50176 B

__global__ void upconv_cropcat_kernel(const float* __restrict__ x,
                                      const float* __restrict__ z,
                                      const float* __restrict__ W,
                                      const float* __restrict__ b,
                                      float* __restrict__ out)
{
    extern __shared__ __align__(16) float dynsmem[];

    const int bid  = blockIdx.x;
    const int tid  = threadIdx.x;
    const int warp = tid >> 5;
    const int lane = tid & 31;

    if (bid % 5 == 0) {
        // =============== conv block: (dp, hq), 2 h' rows, full 64 w' ========
        float* Wt = dynsmem;                    // [c][o], pitch 68
        float* ys = dynsmem + 64 * WT_PITCH;    // [o][hp][w'], 32 KB

        const int aid = bid / 5;        // 0..1023
        const int dp  = aid >> 5;       // 0..31
        const int hq  = aid & 31;       // 0..31  (h' = 2hq, 2hq+1)

        // Stage W transposed: Wt[c][o] = W[o][c].
        const float4* __restrict__ W4 = (const float4*)W;
        #pragma unroll
        for (int i = tid; i < 1024; i += 256) {
            float4 v = W4[i];
            int o  = i >> 4;            // 0..63
            int c4 = (i & 15) << 2;     // 0..60
            Wt[(c4 + 0) * WT_PITCH + o] = v.x;
            Wt[(c4 + 1) * WT_PITCH + o] = v.y;
            Wt[(c4 + 2) * WT_PITCH + o] = v.z;
            Wt[(c4 + 3) * WT_PITCH + o] = v.w;
        }
        __syncthreads();

        const int wo = tid & 15;        // w-quad: w' = wo*4 .. +3
        const int oq = tid >> 4;        // 0..15, o = oq*4 .. +3
        const float4 bv = __ldg((const float4*)b + oq);
        const float4* __restrict__ Wt4 = (const float4*)Wt;
        // x row base for this block; x read via L1 (each 256B row shared by
        // all 8 warps -> one DRAM read, then L1 hits).
        const float4* __restrict__ xbase4 =
            (const float4*)(x + dp * (XH * XW)) + wo;

        #pragma unroll
        for (int hp = 0; hp < 2; hp++) {
            const float4* __restrict__ xr = xbase4 + (hq * 2 + hp) * (XW / 4);

            unsigned long long acc[4][2];
            #pragma unroll
            for (int j = 0; j < 4; j++) { acc[j][0] = 0ull; acc[j][1] = 0ull; }

            #pragma unroll 4
            for (int c = 0; c < 64; c++) {
                float4 xv = __ldg(xr + c * (X_CH_STRIDE / 4));
                float4 wv = Wt4[c * (WT_PITCH / 4) + oq];
                unsigned x0 = __float_as_uint(xv.x), x1 = __float_as_uint(xv.y);
                unsigned x2 = __float_as_uint(xv.z), x3 = __float_as_uint(xv.w);
                unsigned w0u = __float_as_uint(wv.x), w1u = __float_as_uint(wv.y);
                unsigned w2u = __float_as_uint(wv.z), w3u = __float_as_uint(wv.w);
                asm volatile(
                    "{\n\t"
                    ".reg .b64 xa, xb, wd;\n\t"
                    "mov.b64 xa, {%8, %9};\n\t"
                    "mov.b64 xb, {%10, %11};\n\t"
                    "mov.b64 wd, {%12, %12};\n\t"
                    "fma.rn.f32x2 %0, wd, xa, %0;\n\t"
                    "fma.rn.f32x2 %1, wd, xb, %1;\n\t"
                    "mov.b64 wd, {%13, %13};\n\t"
                    "fma.rn.f32x2 %2, wd, xa, %2;\n\t"
                    "fma.rn.f32x2 %3, wd, xb, %3;\n\t"
                    "mov.b64 wd, {%14, %14};\n\t"
                    "fma.rn.f32x2 %4, wd, xa, %4;\n\t"
                    "fma.rn.f32x2 %5, wd, xb, %5;\n\t"
                    "mov.b64 wd, {%15, %15};\n\t"
                    "fma.rn.f32x2 %6, wd, xa, %6;\n\t"
                    "fma.rn.f32x2 %7, wd, xb, %7;\n\t"
                    "}"
                    : "+l"(acc[0][0]), "+l"(acc[0][1]),
                      "+l"(acc[1][0]), "+l"(acc[1][1]),
                      "+l"(acc[2][0]), "+l"(acc[2][1]),
                      "+l"(acc[3][0]), "+l"(acc[3][1])
                    : "r"(x0), "r"(x1), "r"(x2), "r"(x3),
                      "r"(w0u), "r"(w1u), "r"(w2u), "r"(w3u));
            }

            // Stage un-duplicated results (+bias) into ys[o][hp][w'].
            #pragma unroll
            for (int j = 0; j < 4; j++) {
                unsigned u0, u1, u2, u3;
                asm("mov.b64 {%0, %1}, %2;" : "=r"(u0), "=r"(u1) : "l"(acc[j][0]));
                asm("mov.b64 {%0, %1}, %2;" : "=r"(u2), "=r"(u3) : "l"(acc[j][1]));
                const float bb = (j == 0) ? bv.x : (j == 1) ? bv.y
                                : (j == 2) ? bv.z : bv.w;
                float4 v = make_float4(__uint_as_float(u0) + bb,
                                       __uint_as_float(u1) + bb,
                                       __uint_as_float(u2) + bb,
                                       __uint_as_float(u3) + bb);
                *(float4*)&ys[(oq * 4 + j) * 128 + hp * 64 + wo * 4] = v;
            }
        }
        __syncthreads();

        // Sweep: each warp writes 16 (o,dd) pairs; per pair a 2 KB contiguous
        // span out[o, 2dp+dd, 4hq .. 4hq+3, :] with lane-sequential STG.128.
        const int p0 = warp * 16;
        #pragma unroll 1
        for (int p = p0; p < p0 + 16; p++) {
            const int o  = p >> 1;
            const int dd = p & 1;
            float* orow = out + (size_t)o * O_CH_STRIDE
                              + (size_t)(2 * dp + dd) * (OH * OW)
                              + (4 * hq) * OW + lane * 4;
            const float* yrow = ys + o * 128 + lane * 2;
            #pragma unroll
            for (int r = 0; r < 4; r++) {
                float2 s = *(const float2*)(yrow + (r >> 1) * 64);
                __stcs((float4*)(orow + r * OW),
                       make_float4(s.x, s.x, s.y, s.y));
            }
        }
    } else {
        // =============== crop-copy block (R8 body, unchanged) ===============
        // out[64+c, d, h, 0:128] = z[c, d+2, h+2, 2:130]
        const int cid = bid - bid / 5 - 1;      // 0..4095
        const int r0 = (cid * 8 + warp) * 16;   // 32768 warps * 16 rows

        const int c   = r0 >> 13;        // / (64*128)
        const int rem = r0 & 8191;
        const int d   = rem >> 7;
        const int h0  = rem & 127;

        const float* src =
            z + ((size_t)((c * ZD + d + 2) * ZH + (h0 + 2))) * ZW + 2 + lane * 4;
        float* dst = out + (size_t)(64 + c) * O_CH_STRIDE
                         + (size_t)d * (OH * OW) + h0 * OW + lane * 4;

        #pragma unroll
        for (int jj = 0; jj < 16; jj += 8) {
            float2 a[8], bb2[8];
            #pragma unroll
            for (int i = 0; i < 8; i++) {
                const float* s = src + (jj + i) * ZW;
                a[i]   = __ldcs((const float2*)s);
                bb2[i] = __ldcs((const float2*)(s + 2));
            }
            #pragma unroll
            for (int i = 0; i < 8; i++) {
                __stcs((float4*)(dst + (jj + i) * OW),
                       make_float4(a[i].x, a[i].y, bb2[i].x, bb2[i].y));
            }
        }
    }
}

extern "C" void kernel_launch(void* const* d_in, const int* in_sizes, int n_in,
                              void* d_out, int out_size)
{
    const float* x = (const float*)d_in[0];   // (1,64,32,64,64)
    const float* z = (const float*)d_in[1];   // (1,64,68,132,132)
    const float* W = (const float*)d_in[2];   // (64,64)
    const float* b = (const float*)d_in[3];   // (64,)
    float* out = (float*)d_out;               // (1,128,64,128,128)

    // Host-side attribute set (not a stream op; graph-capture legal, idempotent).
    cudaFuncSetAttribute(upconv_cropcat_kernel,
                         cudaFuncAttributeMaxDynamicSharedMemorySize, SMEM_BYTES);
    upconv_cropcat_kernel<<<NUM_BLOCKS, 256, SMEM_BYTES>>>(x, z, W, b, out);
}

// round 17
// speedup vs baseline: 1.3476x; 1.3476x over previous
#include <cuda_runtime.h>
#include <cuda_bf16.h>

// Problem constants
#define C_IN  64
#define C_OUT 64
#define XD 32
#define XH 64
#define XW 64
#define OD 64
#define OH 128
#define OW 128
#define ZD 68
#define ZH 132
#define ZW 132

#define X_CH_STRIDE (XD*XH*XW)      // 131072
#define O_CH_STRIDE (OD*OH*OW)      // 1048576

#define NUM_CONV_BLOCKS 4096        // 32 d' * 64 h' * 2 half-planes
#define NUM_COPY_BLOCKS 8192        // 64 rows each (finer steal granularity)
#define NUM_BLOCKS (NUM_CONV_BLOCKS + NUM_COPY_BLOCKS)   // 12288; 1-in-3 conv

// Wt row pitch in floats. MUST be >= 64 (R12 lesson: pitch<64 overlaps rows).
// 66 = even (8B-aligned float2 reads), 66 mod 32 = 2 -> conflict-free.
#define WT_PITCH 66

__global__ __launch_bounds__(256)
void upconv_cropcat_kernel(const float* __restrict__ x,
                           const float* __restrict__ z,
                           const float* __restrict__ W,
                           const float* __restrict__ b,
                           float* __restrict__ out)
{
    __shared__ __align__(16) float xs[64 * 32];        // [c][w'] tile, 8 KB
    __shared__ __align__(16) float Wt[64 * WT_PITCH];  // [c][o] transposed, 16.5 KB
    __shared__ float bs[64];

    const int bid = blockIdx.x;
    const int tid = threadIdx.x;

    if (bid % 3 == 0) {
        // ------------------- conv part: half of one (d', h') plane -----------
        const int aid  = bid / 3;         // 0..4095
        const int dp   = aid >> 7;        // 0..31
        const int hp   = (aid >> 1) & 63; // 0..63
        const int half = aid & 1;         // w' offset 0 or 32

        // Stage W transposed: Wt[c][o] = W[o][c].
        const float4* __restrict__ W4 = (const float4*)W;
        #pragma unroll
        for (int i = tid; i < 1024; i += 256) {
            float4 v = W4[i];
            int o  = i >> 4;            // 0..63
            int c4 = (i & 15) << 2;     // 0..60
            Wt[(c4 + 0) * WT_PITCH + o] = v.x;
            Wt[(c4 + 1) * WT_PITCH + o] = v.y;
            Wt[(c4 + 2) * WT_PITCH + o] = v.z;
            Wt[(c4 + 3) * WT_PITCH + o] = v.w;
        }

        // Stage x tile: 64 channels x 32 w' (contiguous per channel).
        const float* __restrict__ xbase =
            x + dp * (XH * XW) + hp * XW + half * 32;
        float4* xs4 = (float4*)xs;
        #pragma unroll
        for (int i = tid; i < 512; i += 256) {
            int c  = i >> 3;
            int w4 = i & 7;
            xs4[i] = *(const float4*)(xbase + (size_t)c * X_CH_STRIDE + w4 * 4);
        }
        if (tid < 64) bs[tid] = b[tid];
        __syncthreads();

        // Each thread: 2 output channels x 4 small-w values, packed f32x2.
        const int wo = tid & 7;    // w-quad: w' = half*32 + wo*4 .. +3
        const int oo = tid >> 3;   // o-pair: o = oo*2, oo*2+1

        const unsigned xs_addr =
            (unsigned)__cvta_generic_to_shared(xs) + wo * 16;

        unsigned long long acc00 = 0ull, acc01 = 0ull;  // o0: {w0,w1},{w2,w3}
        unsigned long long acc10 = 0ull, acc11 = 0ull;  // o1

        #pragma unroll 8
        for (int c = 0; c < 64; c++) {
            float2 wv = *(const float2*)&Wt[c * WT_PITCH + oo * 2];
            unsigned w0u = __float_as_uint(wv.x);
            unsigned w1u = __float_as_uint(wv.y);
            asm volatile(
                "{\n\t"
                ".reg .b64 xa, xb, wda, wdb;\n\t"
                "ld.shared.v2.b64 {xa, xb}, [%4];\n\t"
                "mov.b64 wda, {%5, %5};\n\t"
                "mov.b64 wdb, {%6, %6};\n\t"
                "fma.rn.f32x2 %0, wda, xa, %0;\n\t"
                "fma.rn.f32x2 %1, wda, xb, %1;\n\t"
                "fma.rn.f32x2 %2, wdb, xa, %2;\n\t"
                "fma.rn.f32x2 %3, wdb, xb, %3;\n\t"
                "}"
                : "+l"(acc00), "+l"(acc01), "+l"(acc10), "+l"(acc11)
                : "r"(xs_addr + c * 128), "r"(w0u), "r"(w1u));
        }

        // Epilogue: unpack, add bias, duplicate 2x along w, write 4 rows each.
        #pragma unroll
        for (int j = 0; j < 2; j++) {
            const int o = oo * 2 + j;
            const float bb = bs[o];
            unsigned u0, u1, u2, u3;
            if (j == 0) {
                asm("mov.b64 {%0, %1}, %2;" : "=r"(u0), "=r"(u1) : "l"(acc00));
                asm("mov.b64 {%0, %1}, %2;" : "=r"(u2), "=r"(u3) : "l"(acc01));
            } else {
                asm("mov.b64 {%0, %1}, %2;" : "=r"(u0), "=r"(u1) : "l"(acc10));
                asm("mov.b64 {%0, %1}, %2;" : "=r"(u2), "=r"(u3) : "l"(acc11));
            }
            float v0 = __uint_as_float(u0) + bb;
            float v1 = __uint_as_float(u1) + bb;
            float v2 = __uint_as_float(u2) + bb;
            float v3 = __uint_as_float(u3) + bb;
            float4 lo = make_float4(v0, v0, v1, v1);
            float4 hi = make_float4(v2, v2, v3, v3);
            float* obase = out + (size_t)o * O_CH_STRIDE
                               + (size_t)(2 * dp) * (OH * OW)
                               + (2 * hp) * OW + half * 64 + wo * 8;
            #pragma unroll
            for (int dd = 0; dd < 2; dd++) {
                #pragma unroll
                for (int hh = 0; hh < 2; hh++) {
                    float* p = obase + dd * (OH * OW) + hh * OW;
                    __stcs((float4*)p,     lo);
                    __stcs((float4*)(p+4), hi);
                }
            }
        }
    } else {
        // ------------------- crop-copy part (proven body, 64 rows/block) -----
        // out[64+c, d, h, 0:128] = z[c, d+2, h+2, 2:130]
        // Each warp: 8 h-consecutive rows in one (c,d) plane, one batch of
        // 16 LDG.64 in flight before the 8 STG.128 (R8 in-flight profile).
        const int cid  = bid - bid / 3 - 1;     // 0..8191
        const int warp = tid >> 5;
        const int lane = tid & 31;
        const int r0 = (cid * 8 + warp) * 8;    // 65536 warps * 8 = 524288 rows

        const int c   = r0 >> 13;        // / (64*128)
        const int rem = r0 & 8191;
        const int d   = rem >> 7;
        const int h0  = rem & 127;

        const float* src =
            z + ((size_t)((c * ZD + d + 2) * ZH + (h0 + 2))) * ZW + 2 + lane * 4;
        float* dst = out + (size_t)(64 + c) * O_CH_STRIDE
                         + (size_t)d * (OH * OW) + h0 * OW + lane * 4;

        float2 a[8], bb2[8];
        #pragma unroll
        for (int i = 0; i < 8; i++) {
            const float* s = src + i * ZW;
            a[i]   = __ldcs((const float2*)s);
            bb2[i] = __ldcs((const float2*)(s + 2));
        }
        #pragma unroll
        for (int i = 0; i < 8; i++) {
            __stcs((float4*)(dst + i * OW),
                   make_float4(a[i].x, a[i].y, bb2[i].x, bb2[i].y));
        }
    }
}

extern "C" void kernel_launch(void* const* d_in, const int* in_sizes, int n_in,
                              void* d_out, int out_size)
{
    const float* x = (const float*)d_in[0];   // (1,64,32,64,64)
    const float* z = (const float*)d_in[1];   // (1,64,68,132,132)
    const float* W = (const float*)d_in[2];   // (64,64)
    const float* b = (const float*)d_in[3];   // (64,)
    float* out = (float*)d_out;               // (1,128,64,128,128)

    upconv_cropcat_kernel<<<NUM_BLOCKS, 256>>>(x, z, W, b, out);
}